// round 11
// baseline (speedup 1.0000x reference)
#include <cuda_runtime.h>
#include <cstdint>

#define SEQ   2048
#define BATCH 32
#define IDIM  256
#define HDIM  256
#define G4    1024

// 268 MB scratch for precomputed input projections: Xg[t][b][g]
__device__ float g_xg[SEQ * BATCH * G4];

// ---------------------------------------------------------------------------
// Kernel 1 (unchanged control): Xg = x @ W_ih^T + b_ih + b_hh
// ---------------------------------------------------------------------------
#define BM 64
#define BN 64
#define BK 32

__global__ __launch_bounds__(256) void xproj_kernel(
    const float* __restrict__ x,
    const float* __restrict__ Wih,
    const float* __restrict__ bih,
    const float* __restrict__ bhh)
{
    __shared__ float As[BK][BM];
    __shared__ float Bs[BK][BN];

    const int tid  = threadIdx.x;
    const int mblk = blockIdx.x;
    const int nblk = blockIdx.y;

    const float* Arow = x   + (size_t)mblk * BM * IDIM;
    const float* Brow = Wih + (size_t)nblk * BN * IDIM;

    const int tx = tid & 15;
    const int ty = tid >> 4;

    float acc[4][4] = {};

    const int lr  = tid >> 2;
    const int lkq = (tid & 3) * 8;

    for (int k0 = 0; k0 < IDIM; k0 += BK) {
        {
            float4 v0 = *(const float4*)(Arow + lr * IDIM + k0 + lkq);
            float4 v1 = *(const float4*)(Arow + lr * IDIM + k0 + lkq + 4);
            As[lkq + 0][lr] = v0.x; As[lkq + 1][lr] = v0.y;
            As[lkq + 2][lr] = v0.z; As[lkq + 3][lr] = v0.w;
            As[lkq + 4][lr] = v1.x; As[lkq + 5][lr] = v1.y;
            As[lkq + 6][lr] = v1.z; As[lkq + 7][lr] = v1.w;

            float4 w0 = *(const float4*)(Brow + lr * IDIM + k0 + lkq);
            float4 w1 = *(const float4*)(Brow + lr * IDIM + k0 + lkq + 4);
            Bs[lkq + 0][lr] = w0.x; Bs[lkq + 1][lr] = w0.y;
            Bs[lkq + 2][lr] = w0.z; Bs[lkq + 3][lr] = w0.w;
            Bs[lkq + 4][lr] = w1.x; Bs[lkq + 5][lr] = w1.y;
            Bs[lkq + 6][lr] = w1.z; Bs[lkq + 7][lr] = w1.w;
        }
        __syncthreads();

        #pragma unroll
        for (int kk = 0; kk < BK; kk++) {
            float4 av = *(const float4*)&As[kk][ty * 4];
            float4 bv = *(const float4*)&Bs[kk][tx * 4];
            float a[4] = {av.x, av.y, av.z, av.w};
            float b[4] = {bv.x, bv.y, bv.z, bv.w};
            #pragma unroll
            for (int i = 0; i < 4; i++)
                #pragma unroll
                for (int jj = 0; jj < 4; jj++)
                    acc[i][jj] = fmaf(a[i], b[jj], acc[i][jj]);
        }
        __syncthreads();
    }

    const int mb = mblk * BM + ty * 4;
    const int nb = nblk * BN + tx * 4;
    float bias[4];
    #pragma unroll
    for (int jj = 0; jj < 4; jj++)
        bias[jj] = bih[nb + jj] + bhh[nb + jj];

    #pragma unroll
    for (int i = 0; i < 4; i++) {
        float4 v;
        v.x = acc[i][0] + bias[0];
        v.y = acc[i][1] + bias[1];
        v.z = acc[i][2] + bias[2];
        v.w = acc[i][3] + bias[3];
        *(float4*)&g_xg[(size_t)(mb + i) * G4 + nb] = v;
    }
}

// ---------------------------------------------------------------------------
// Kernel 2: recurrence. Split barrier; owners = warps 14/15 (hi-wid arbiter
// priority); xg software-pipelined one step ahead; all-8 st.async broadcast
// (race-free: every h write is mbarrier-tx-counted).
// ---------------------------------------------------------------------------
__device__ __forceinline__ void ffma2(uint64_t& acc, uint64_t a, uint64_t b) {
    asm("fma.rn.f32x2 %0, %1, %2, %0;" : "+l"(acc) : "l"(a), "l"(b));
}
__device__ __forceinline__ float hsum2(uint64_t a) {
    uint32_t lo, hi;
    asm("mov.b64 {%0,%1}, %2;" : "=r"(lo), "=r"(hi) : "l"(a));
    return __uint_as_float(lo) + __uint_as_float(hi);
}
__device__ __forceinline__ void mbar_wait(uint32_t addr, unsigned par) {
    asm volatile(
        "{\n\t"
        ".reg .pred P;\n\t"
        "WAIT_%=:\n\t"
        "mbarrier.try_wait.parity.acquire.cta.shared::cta.b64 P, [%0], %1, 0x989680;\n\t"
        "@P bra DONE_%=;\n\t"
        "bra WAIT_%=;\n\t"
        "DONE_%=:\n\t"
        "}"
        :: "r"(addr), "r"(par) : "memory");
}

#define TX_PER_BUF 2048   // 8 ranks x 64 floats x 4 B

__global__ void __cluster_dims__(8, 1, 1) __launch_bounds__(512, 1)
lstm_rec_kernel(const float* __restrict__ Whh,
                const float* __restrict__ h0,
                const float* __restrict__ c0,
                float* __restrict__ out)
{
    __shared__ float h_s[2][2][HDIM];        // [buf][local batch][k]
    __shared__ float red_s[2][4][2][128];    // [rd][kseg][bb][local row]
    __shared__ alignas(8) unsigned long long mbar[2];

    const int tid  = threadIdx.x;
    const int lane = tid & 31;
    const int w    = tid >> 5;
    const int kseg = w >> 2;
    const int lr   = (w & 3) * 32 + lane;

    unsigned rank;
    asm("mov.u32 %0, %%cluster_ctarank;" : "=r"(rank));
    const int b0 = (blockIdx.x >> 3) * 2;
    const int R  = ((lr >> 5) << 8) + (int)rank * 32 + (lr & 31);

    // ---- W_hh slice into registers: 64 floats -> 32 u64 k-pairs ----
    uint64_t wp[32];
    {
        const float* W = Whh + (size_t)R * HDIM + kseg * 64;
        #pragma unroll
        for (int i = 0; i < 16; i++) {
            float4 v = *(const float4*)(W + 4 * i);
            asm("mov.b64 %0, {%1,%2};" : "=l"(wp[2*i+0]) : "f"(v.x), "f"(v.y));
            asm("mov.b64 %0, {%1,%2};" : "=l"(wp[2*i+1]) : "f"(v.z), "f"(v.w));
        }
    }

    // ---- init h_s buf0 with h0 ----
    for (int i = tid; i < 2 * HDIM; i += 512)
        h_s[0][i >> 8][i & 255] = h0[(size_t)(b0 + (i >> 8)) * HDIM + (i & 255)];

    // ---- owners: warps 14/15 (highest arbiter priority) ----
    const bool owner = (w >= 14);
    const int bb = w & 1;                    // w14 -> bb0, w15 -> bb1
    const int j  = lane;
    const int kglob = (int)rank * 32 + j;
    float c_reg = 0.f, h_last = 0.f;
    float xgc0 = 0.f, xgc1 = 0.f, xgc2 = 0.f, xgc3 = 0.f;   // pipelined xg
    if (owner) {
        c_reg = c0[(size_t)(b0 + bb) * HDIM + kglob];
        const float* xp = g_xg + ((size_t)(SEQ - 1) * BATCH + b0 + bb) * G4 + kglob;
        xgc0 = __ldg(xp);
        xgc1 = __ldg(xp + 256);
        xgc2 = __ldg(xp + 512);
        xgc3 = __ldg(xp + 768);
    }

    const uint32_t h_base  = (uint32_t)__cvta_generic_to_shared(&h_s[0][0][0]);
    const uint32_t mb_addr = (uint32_t)__cvta_generic_to_shared(&mbar[0]);
    const uint32_t mb_delta = mb_addr - h_base;

    if (tid == 0) {
        asm volatile("mbarrier.init.shared.b64 [%0], %1;" :: "r"(mb_addr), "r"(1) : "memory");
        asm volatile("mbarrier.init.shared.b64 [%0], %1;" :: "r"(mb_addr + 8), "r"(1) : "memory");
        asm volatile("mbarrier.arrive.expect_tx.shared.b64 _, [%0], %1;" :: "r"(mb_addr), "r"(TX_PER_BUF) : "memory");
        asm volatile("mbarrier.arrive.expect_tx.shared.b64 _, [%0], %1;" :: "r"(mb_addr + 8), "r"(TX_PER_BUF) : "memory");
    }
    // hoisted mapa of h_base per rank
    uint32_t ph[8];
    #pragma unroll
    for (int r = 0; r < 8; r++)
        asm("mapa.shared::cluster.u32 %0, %1, %2;" : "=r"(ph[r]) : "r"(h_base), "r"(r));

    __syncthreads();
    asm volatile("barrier.cluster.arrive.aligned;" ::: "memory");
    asm volatile("barrier.cluster.wait.aligned;" ::: "memory");

    auto step = [&](int t, int rd, bool dowait, unsigned par, bool dostore) {
        // prefetch NEXT step's xg (full step duration to cover DRAM)
        float nx0 = 0.f, nx1 = 0.f, nx2 = 0.f, nx3 = 0.f;
        if (owner && t > 0) {
            const float* xp = g_xg + ((size_t)(t - 1) * BATCH + b0 + bb) * G4 + kglob;
            nx0 = __ldg(xp);
            nx1 = __ldg(xp + 256);
            nx2 = __ldg(xp + 512);
            nx3 = __ldg(xp + 768);
        }

        const uint32_t mb_rd = mb_addr + (uint32_t)rd * 8;
        if (dowait) {
            mbar_wait(mb_rd, par);
            if (tid == 0)
                asm volatile("mbarrier.arrive.expect_tx.shared.b64 _, [%0], %1;"
                             :: "r"(mb_rd), "r"(TX_PER_BUF) : "memory");
        }

        // ---- k-loop: 64 K x 2 batches, weights in regs, broadcast LDS ----
        const uint32_t a0 = h_base + (uint32_t)(rd * 512 + kseg * 64) * 4;
        const uint32_t a1 = a0 + 1024;
        uint64_t acc0 = 0ull, acc1 = 0ull;
        #pragma unroll
        for (int i = 0; i < 64; i += 4) {
            uint64_t u01, u23, v01, v23;
            asm volatile("ld.shared.v2.u64 {%0,%1}, [%2];"
                         : "=l"(u01), "=l"(u23) : "r"(a0 + i * 4));
            asm volatile("ld.shared.v2.u64 {%0,%1}, [%2];"
                         : "=l"(v01), "=l"(v23) : "r"(a1 + i * 4));
            ffma2(acc0, wp[i / 2 + 0], u01);
            ffma2(acc1, wp[i / 2 + 0], v01);
            ffma2(acc0, wp[i / 2 + 1], u23);
            ffma2(acc1, wp[i / 2 + 1], v23);
        }
        red_s[rd][kseg][0][lr] = hsum2(acc0);
        red_s[rd][kseg][1][lr] = hsum2(acc1);

        if (!owner) {
            // non-owners: post results and immediately move to next step
            asm volatile("bar.arrive 1, 512;" ::: "memory");
            return;
        }

        // owners: wait for all 16 warps' red_s
        asm volatile("bar.sync 1, 512;" ::: "memory");

        float s0 = xgc0, s1 = xgc1, s2 = xgc2, s3 = xgc3;
        #pragma unroll
        for (int ks = 0; ks < 4; ks++) {
            s0 += red_s[rd][ks][bb][ 0 + j];
            s1 += red_s[rd][ks][bb][32 + j];
            s2 += red_s[rd][ks][bb][64 + j];
            s3 += red_s[rd][ks][bb][96 + j];
        }
        xgc0 = nx0; xgc1 = nx1; xgc2 = nx2; xgc3 = nx3;

        const float ig = __fdividef(1.f, 1.f + __expf(-s0));
        const float fg = __fdividef(1.f, 1.f + __expf(-s1));
        const float gt = 1.f - 2.f * __fdividef(1.f, 1.f + __expf(2.f * s2));
        const float og = __fdividef(1.f, 1.f + __expf(-s3));

        c_reg = fg * c_reg + ig * gt;
        const float h = og * (1.f - 2.f * __fdividef(1.f, 1.f + __expf(2.f * c_reg)));
        h_last = h;

        if (dostore) {
            const int wr = rd ^ 1;
            const uint32_t hoff = (uint32_t)(((wr * 2 + bb) * 256 + kglob) * 4);
            const uint32_t moff = mb_delta + (uint32_t)wr * 8;
            // all 8 ranks via st.async (every write tx-counted: race-free)
            #pragma unroll
            for (int r = 0; r < 8; r++) {
                asm volatile(
                    "st.async.shared::cluster.mbarrier::complete_tx::bytes.b32 [%0], %1, [%2];"
                    :: "r"(ph[r] + hoff), "f"(h), "r"(ph[r] + moff) : "memory");
            }
        }

        out[((size_t)t * BATCH + b0 + bb) * HDIM + kglob] = h;
    };

    // rd(t) = (t+1)&1. Loop pairs (even t, odd t-1) down to (2, 1); peel t=0.
    unsigned par0 = 0, par1 = 0;
    step(SEQ - 1, 0, false, 0, true);                   // t=2047, rd=0
    for (int t = SEQ - 2; t >= 2; t -= 2) {
        step(t,     1, true, par1, true);  par1 ^= 1;   // even t, rd=1
        step(t - 1, 0, true, par0, true);  par0 ^= 1;   // odd t-1, rd=0
    }
    step(0, 1, true, par1, false);                      // t=0, rd=1

    if (owner) {
        float* hT = out + (size_t)SEQ * BATCH * HDIM;
        float* cT = hT + (size_t)BATCH * HDIM;
        hT[(size_t)(b0 + bb) * HDIM + kglob] = h_last;
        cT[(size_t)(b0 + bb) * HDIM + kglob] = c_reg;
    }
}

// ---------------------------------------------------------------------------
extern "C" void kernel_launch(void* const* d_in, const int* in_sizes, int n_in,
                              void* d_out, int out_size)
{
    (void)in_sizes; (void)n_in; (void)out_size;
    const float* x   = (const float*)d_in[0];
    const float* h0  = (const float*)d_in[1];
    const float* c0  = (const float*)d_in[2];
    const float* Wih = (const float*)d_in[3];
    const float* Whh = (const float*)d_in[4];
    const float* bih = (const float*)d_in[5];
    const float* bhh = (const float*)d_in[6];
    float* out = (float*)d_out;

    dim3 gridP(65536 / BM, G4 / BN);   // (1024, 16)
    xproj_kernel<<<gridP, 256>>>(x, Wih, bih, bhh);

    lstm_rec_kernel<<<128, 512>>>(Whh, h0, c0, out);
}

// round 12
// speedup vs baseline: 1.1290x; 1.1290x over previous
#include <cuda_runtime.h>
#include <cstdint>

#define SEQ   2048
#define BATCH 32
#define IDIM  256
#define HDIM  256
#define G4    1024

// 268 MB scratch for precomputed input projections: Xg[t][b][g]
__device__ float g_xg[SEQ * BATCH * G4];

__device__ __forceinline__ void ffma2(uint64_t& acc, uint64_t a, uint64_t b) {
    asm("fma.rn.f32x2 %0, %1, %2, %0;" : "+l"(acc) : "l"(a), "l"(b));
}
__device__ __forceinline__ float hsum2(uint64_t a) {
    uint32_t lo, hi;
    asm("mov.b64 {%0,%1}, %2;" : "=r"(lo), "=r"(hi) : "l"(a));
    return __uint_as_float(lo) + __uint_as_float(hi);
}

// ---------------------------------------------------------------------------
// Kernel 1: Xg = x @ W_ih^T + b_ih + b_hh  (FFMA2 microtile)
// ---------------------------------------------------------------------------
#define BM 64
#define BN 64
#define BK 32

__global__ __launch_bounds__(256) void xproj_kernel(
    const float* __restrict__ x,
    const float* __restrict__ Wih,
    const float* __restrict__ bih,
    const float* __restrict__ bhh)
{
    __shared__ float As[BK][BM];
    __shared__ float Bs[BK][BN];

    const int tid  = threadIdx.x;
    const int mblk = blockIdx.x;
    const int nblk = blockIdx.y;

    const float* Arow = x   + (size_t)mblk * BM * IDIM;
    const float* Brow = Wih + (size_t)nblk * BN * IDIM;

    const int tx = tid & 15;
    const int ty = tid >> 4;

    // packed accumulators: rows i=0..3, col-pairs {n0,n1} and {n2,n3}
    uint64_t acc01[4] = {}, acc23[4] = {};

    const int lr  = tid >> 2;
    const int lkq = (tid & 3) * 8;

    for (int k0 = 0; k0 < IDIM; k0 += BK) {
        {
            float4 v0 = *(const float4*)(Arow + lr * IDIM + k0 + lkq);
            float4 v1 = *(const float4*)(Arow + lr * IDIM + k0 + lkq + 4);
            As[lkq + 0][lr] = v0.x; As[lkq + 1][lr] = v0.y;
            As[lkq + 2][lr] = v0.z; As[lkq + 3][lr] = v0.w;
            As[lkq + 4][lr] = v1.x; As[lkq + 5][lr] = v1.y;
            As[lkq + 6][lr] = v1.z; As[lkq + 7][lr] = v1.w;

            float4 w0 = *(const float4*)(Brow + lr * IDIM + k0 + lkq);
            float4 w1 = *(const float4*)(Brow + lr * IDIM + k0 + lkq + 4);
            Bs[lkq + 0][lr] = w0.x; Bs[lkq + 1][lr] = w0.y;
            Bs[lkq + 2][lr] = w0.z; Bs[lkq + 3][lr] = w0.w;
            Bs[lkq + 4][lr] = w1.x; Bs[lkq + 5][lr] = w1.y;
            Bs[lkq + 6][lr] = w1.z; Bs[lkq + 7][lr] = w1.w;
        }
        __syncthreads();

        #pragma unroll
        for (int kk = 0; kk < BK; kk++) {
            float4 av = *(const float4*)&As[kk][ty * 4];
            const uint64_t b01 = *(const uint64_t*)&Bs[kk][tx * 4];
            const uint64_t b23 = *(const uint64_t*)&Bs[kk][tx * 4 + 2];
            float a[4] = {av.x, av.y, av.z, av.w};
            #pragma unroll
            for (int i = 0; i < 4; i++) {
                uint64_t aa;
                asm("mov.b64 %0, {%1,%1};" : "=l"(aa) : "f"(a[i]));
                ffma2(acc01[i], aa, b01);
                ffma2(acc23[i], aa, b23);
            }
        }
        __syncthreads();
    }

    const int mb = mblk * BM + ty * 4;
    const int nb = nblk * BN + tx * 4;
    float bias[4];
    #pragma unroll
    for (int jj = 0; jj < 4; jj++)
        bias[jj] = bih[nb + jj] + bhh[nb + jj];

    #pragma unroll
    for (int i = 0; i < 4; i++) {
        uint32_t lo, hi, lo2, hi2;
        asm("mov.b64 {%0,%1}, %2;" : "=r"(lo), "=r"(hi) : "l"(acc01[i]));
        asm("mov.b64 {%0,%1}, %2;" : "=r"(lo2), "=r"(hi2) : "l"(acc23[i]));
        float4 v;
        v.x = __uint_as_float(lo)  + bias[0];
        v.y = __uint_as_float(hi)  + bias[1];
        v.z = __uint_as_float(lo2) + bias[2];
        v.w = __uint_as_float(hi2) + bias[3];
        *(float4*)&g_xg[(size_t)(mb + i) * G4 + nb] = v;
    }
}

// ---------------------------------------------------------------------------
// Kernel 2: recurrence (R9 skeleton). Split barrier; owners = warps 0/1;
// in-step xg loads; broadcast via b64-PACKED st.async to all 8 ranks
// (256 messages/dest vs 512 — every h write tx-counted, race-free).
// ---------------------------------------------------------------------------
__device__ __forceinline__ void mbar_wait(uint32_t addr, unsigned par) {
    asm volatile(
        "{\n\t"
        ".reg .pred P;\n\t"
        "WAIT_%=:\n\t"
        "mbarrier.try_wait.parity.acquire.cta.shared::cta.b64 P, [%0], %1, 0x989680;\n\t"
        "@P bra DONE_%=;\n\t"
        "bra WAIT_%=;\n\t"
        "DONE_%=:\n\t"
        "}"
        :: "r"(addr), "r"(par) : "memory");
}

#define TX_PER_BUF 2048   // 8 ranks x 32 pairs x 8 B

__global__ void __cluster_dims__(8, 1, 1) __launch_bounds__(512, 1)
lstm_rec_kernel(const float* __restrict__ Whh,
                const float* __restrict__ h0,
                const float* __restrict__ c0,
                float* __restrict__ out)
{
    __shared__ float h_s[2][2][HDIM];        // [buf][local batch][k]
    __shared__ float red_s[2][4][2][128];    // [rd][kseg][bb][local row]
    __shared__ alignas(8) unsigned long long mbar[2];

    const int tid  = threadIdx.x;
    const int lane = tid & 31;
    const int w    = tid >> 5;
    const int kseg = w >> 2;
    const int lr   = (w & 3) * 32 + lane;

    unsigned rank;
    asm("mov.u32 %0, %%cluster_ctarank;" : "=r"(rank));
    const int b0 = (blockIdx.x >> 3) * 2;
    const int R  = ((lr >> 5) << 8) + (int)rank * 32 + (lr & 31);

    // ---- W_hh slice into registers: 64 floats -> 32 u64 k-pairs ----
    uint64_t wp[32];
    {
        const float* W = Whh + (size_t)R * HDIM + kseg * 64;
        #pragma unroll
        for (int i = 0; i < 16; i++) {
            float4 v = *(const float4*)(W + 4 * i);
            asm("mov.b64 %0, {%1,%2};" : "=l"(wp[2*i+0]) : "f"(v.x), "f"(v.y));
            asm("mov.b64 %0, {%1,%2};" : "=l"(wp[2*i+1]) : "f"(v.z), "f"(v.w));
        }
    }

    // ---- init h_s buf0 with h0 ----
    for (int i = tid; i < 2 * HDIM; i += 512)
        h_s[0][i >> 8][i & 255] = h0[(size_t)(b0 + (i >> 8)) * HDIM + (i & 255)];

    // ---- owners (tid < 64): (bb, j) state cell ----
    const int bb = w & 1;
    const int j  = lane;
    const int kglob = (int)rank * 32 + j;
    float c_reg = 0.f, h_last = 0.f;
    if (tid < 64)
        c_reg = c0[(size_t)(b0 + bb) * HDIM + kglob];

    const uint32_t h_base  = (uint32_t)__cvta_generic_to_shared(&h_s[0][0][0]);
    const uint32_t mb_addr = (uint32_t)__cvta_generic_to_shared(&mbar[0]);
    const uint32_t mb_delta = mb_addr - h_base;

    if (tid == 0) {
        asm volatile("mbarrier.init.shared.b64 [%0], %1;" :: "r"(mb_addr), "r"(1) : "memory");
        asm volatile("mbarrier.init.shared.b64 [%0], %1;" :: "r"(mb_addr + 8), "r"(1) : "memory");
        asm volatile("mbarrier.arrive.expect_tx.shared.b64 _, [%0], %1;" :: "r"(mb_addr), "r"(TX_PER_BUF) : "memory");
        asm volatile("mbarrier.arrive.expect_tx.shared.b64 _, [%0], %1;" :: "r"(mb_addr + 8), "r"(TX_PER_BUF) : "memory");
    }
    // hoisted mapa of h_base per rank
    uint32_t ph[8];
    #pragma unroll
    for (int r = 0; r < 8; r++)
        asm("mapa.shared::cluster.u32 %0, %1, %2;" : "=r"(ph[r]) : "r"(h_base), "r"(r));

    __syncthreads();
    asm volatile("barrier.cluster.arrive.aligned;" ::: "memory");
    asm volatile("barrier.cluster.wait.aligned;" ::: "memory");

    auto step = [&](int t, int rd, bool dowait, unsigned par, bool dostore) {
        // xg prefetch (hidden under wait + k-loop)
        float xg0 = 0.f, xg1 = 0.f, xg2 = 0.f, xg3 = 0.f;
        if (tid < 64) {
            const float* xp = g_xg + ((size_t)t * BATCH + b0 + bb) * G4 + kglob;
            xg0 = __ldg(xp);
            xg1 = __ldg(xp + 256);
            xg2 = __ldg(xp + 512);
            xg3 = __ldg(xp + 768);
        }

        const uint32_t mb_rd = mb_addr + (uint32_t)rd * 8;
        if (dowait) {
            mbar_wait(mb_rd, par);
            if (tid == 0)
                asm volatile("mbarrier.arrive.expect_tx.shared.b64 _, [%0], %1;"
                             :: "r"(mb_rd), "r"(TX_PER_BUF) : "memory");
        }

        // ---- k-loop: 64 K x 2 batches, weights in regs, broadcast LDS ----
        const uint32_t a0 = h_base + (uint32_t)(rd * 512 + kseg * 64) * 4;
        const uint32_t a1 = a0 + 1024;
        uint64_t acc0 = 0ull, acc1 = 0ull;
        #pragma unroll
        for (int i = 0; i < 64; i += 4) {
            uint64_t u01, u23, v01, v23;
            asm volatile("ld.shared.v2.u64 {%0,%1}, [%2];"
                         : "=l"(u01), "=l"(u23) : "r"(a0 + i * 4));
            asm volatile("ld.shared.v2.u64 {%0,%1}, [%2];"
                         : "=l"(v01), "=l"(v23) : "r"(a1 + i * 4));
            ffma2(acc0, wp[i / 2 + 0], u01);
            ffma2(acc1, wp[i / 2 + 0], v01);
            ffma2(acc0, wp[i / 2 + 1], u23);
            ffma2(acc1, wp[i / 2 + 1], v23);
        }
        red_s[rd][kseg][0][lr] = hsum2(acc0);
        red_s[rd][kseg][1][lr] = hsum2(acc1);

        if (tid >= 64) {
            // non-owners: post results and immediately move to next step
            asm volatile("bar.arrive 1, 512;" ::: "memory");
            return;
        }

        // owners: wait for all 16 warps' red_s
        asm volatile("bar.sync 1, 512;" ::: "memory");

        float s0 = xg0, s1 = xg1, s2 = xg2, s3 = xg3;
        #pragma unroll
        for (int ks = 0; ks < 4; ks++) {
            s0 += red_s[rd][ks][bb][ 0 + j];
            s1 += red_s[rd][ks][bb][32 + j];
            s2 += red_s[rd][ks][bb][64 + j];
            s3 += red_s[rd][ks][bb][96 + j];
        }
        const float ig = __fdividef(1.f, 1.f + __expf(-s0));
        const float fg = __fdividef(1.f, 1.f + __expf(-s1));
        const float gt = 1.f - 2.f * __fdividef(1.f, 1.f + __expf(2.f * s2));
        const float og = __fdividef(1.f, 1.f + __expf(-s3));

        c_reg = fg * c_reg + ig * gt;
        const float h = og * (1.f - 2.f * __fdividef(1.f, 1.f + __expf(2.f * c_reg)));
        h_last = h;

        if (dostore) {
            // pack pair {h_j, h_j+1}; even lanes store b64 to all 8 ranks
            const float hn = __shfl_down_sync(0xffffffffu, h, 1);
            if ((lane & 1) == 0) {
                uint64_t hp;
                asm("mov.b64 %0, {%1,%2};" : "=l"(hp) : "f"(h), "f"(hn));
                const int wr = rd ^ 1;
                const uint32_t hoff = (uint32_t)(((wr * 2 + bb) * 256 + kglob) * 4);
                const uint32_t moff = mb_delta + (uint32_t)wr * 8;
                #pragma unroll
                for (int r = 0; r < 8; r++) {
                    asm volatile(
                        "st.async.shared::cluster.mbarrier::complete_tx::bytes.b64 [%0], %1, [%2];"
                        :: "r"(ph[r] + hoff), "l"(hp), "r"(ph[r] + moff) : "memory");
                }
            }
        }

        out[((size_t)t * BATCH + b0 + bb) * HDIM + kglob] = h;
    };

    // rd(t) = (t+1)&1. Loop pairs (even t, odd t-1) down to (2, 1); peel t=0.
    unsigned par0 = 0, par1 = 0;
    step(SEQ - 1, 0, false, 0, true);                   // t=2047, rd=0
    for (int t = SEQ - 2; t >= 2; t -= 2) {
        step(t,     1, true, par1, true);  par1 ^= 1;   // even t, rd=1
        step(t - 1, 0, true, par0, true);  par0 ^= 1;   // odd t-1, rd=0
    }
    step(0, 1, true, par1, false);                      // t=0, rd=1

    if (tid < 64) {
        float* hT = out + (size_t)SEQ * BATCH * HDIM;
        float* cT = hT + (size_t)BATCH * HDIM;
        hT[(size_t)(b0 + bb) * HDIM + kglob] = h_last;
        cT[(size_t)(b0 + bb) * HDIM + kglob] = c_reg;
    }
}

// ---------------------------------------------------------------------------
extern "C" void kernel_launch(void* const* d_in, const int* in_sizes, int n_in,
                              void* d_out, int out_size)
{
    (void)in_sizes; (void)n_in; (void)out_size;
    const float* x   = (const float*)d_in[0];
    const float* h0  = (const float*)d_in[1];
    const float* c0  = (const float*)d_in[2];
    const float* Wih = (const float*)d_in[3];
    const float* Whh = (const float*)d_in[4];
    const float* bih = (const float*)d_in[5];
    const float* bhh = (const float*)d_in[6];
    float* out = (float*)d_out;

    dim3 gridP(65536 / BM, G4 / BN);   // (1024, 16)
    xproj_kernel<<<gridP, 256>>>(x, Wih, bih, bhh);

    lstm_rec_kernel<<<128, 512>>>(Whh, h0, c0, out);
}